// round 1
// baseline (speedup 1.0000x reference)
#include <cuda_runtime.h>

#define HID 768
#define SEQ 1024
#define BATCH 8
#define NHEADS 12
#define HDIM 64
#define MTOT (BATCH * SEQ)   // 8192

// Scratch for Q, K, V projections, laid out [M=8192, 768] (row m = b*SEQ+s,
// col o = head*64 + d). 3 x 25.2 MB static device arrays (allowed).
__device__ float g_Q[(size_t)MTOT * HID];
__device__ float g_K[(size_t)MTOT * HID];
__device__ float g_V[(size_t)MTOT * HID];

// ---------------------------------------------------------------------------
// Kernel 1: C = X @ W^T  (both row-major, K-contiguous -> "NT" GEMM)
// BM=128, BN=128, BK=16, 256 threads, 8x8 micro-tile per thread.
// grid = (768/128, 8192/128, 3)  z selects Wq/Wk/Wv.
// ---------------------------------------------------------------------------
__global__ __launch_bounds__(256, 2)
void qkv_gemm(const float* __restrict__ X,
              const float* __restrict__ Wq,
              const float* __restrict__ Wk,
              const float* __restrict__ Wv) {
    __shared__ float As[16][128];   // X tile, transposed: [k][m]
    __shared__ float Bs[16][128];   // W tile, transposed: [k][n]

    const float* W;
    float* C;
    if (blockIdx.z == 0)      { W = Wq; C = g_Q; }
    else if (blockIdx.z == 1) { W = Wk; C = g_K; }
    else                      { W = Wv; C = g_V; }

    const int m0  = blockIdx.y * 128;
    const int n0  = blockIdx.x * 128;
    const int tid = threadIdx.x;
    const int ty  = tid >> 4;          // 0..15 -> output rows ty*8..+7
    const int tx  = tid & 15;          // 0..15 -> output cols tx*8..+7
    const int lrow = tid >> 2;         // 0..63
    const int lcol = (tid & 3) << 2;   // 0,4,8,12

    float acc[8][8];
#pragma unroll
    for (int i = 0; i < 8; i++)
#pragma unroll
        for (int j = 0; j < 8; j++) acc[i][j] = 0.0f;

    for (int k0 = 0; k0 < HID; k0 += 16) {
#pragma unroll
        for (int p = 0; p < 2; p++) {
            int r = lrow + p * 64;
            float4 va = *(const float4*)(X + (size_t)(m0 + r) * HID + k0 + lcol);
            As[lcol + 0][r] = va.x;
            As[lcol + 1][r] = va.y;
            As[lcol + 2][r] = va.z;
            As[lcol + 3][r] = va.w;
            float4 vb = *(const float4*)(W + (size_t)(n0 + r) * HID + k0 + lcol);
            Bs[lcol + 0][r] = vb.x;
            Bs[lcol + 1][r] = vb.y;
            Bs[lcol + 2][r] = vb.z;
            Bs[lcol + 3][r] = vb.w;
        }
        __syncthreads();

#pragma unroll
        for (int kk = 0; kk < 16; kk++) {
            float a[8], b[8];
            *(float4*)(a)     = *(const float4*)&As[kk][ty * 8];
            *(float4*)(a + 4) = *(const float4*)&As[kk][ty * 8 + 4];
            *(float4*)(b)     = *(const float4*)&Bs[kk][tx * 8];
            *(float4*)(b + 4) = *(const float4*)&Bs[kk][tx * 8 + 4];
#pragma unroll
            for (int i = 0; i < 8; i++)
#pragma unroll
                for (int j = 0; j < 8; j++)
                    acc[i][j] += a[i] * b[j];
        }
        __syncthreads();
    }

#pragma unroll
    for (int i = 0; i < 8; i++) {
        int m = m0 + ty * 8 + i;
#pragma unroll
        for (int j = 0; j < 8; j += 4) {
            float4 v = make_float4(acc[i][j], acc[i][j + 1],
                                   acc[i][j + 2], acc[i][j + 3]);
            *(float4*)(C + (size_t)m * HID + n0 + tx * 8 + j) = v;
        }
    }
}

// ---------------------------------------------------------------------------
// Kernel 2: flash-attention-2 style. One block = 64 q-rows of one (b, head).
// 256 threads, 16x16 thread grid, 4x4 micro-tiles. Online softmax.
// smem: Qs (Q^T, pre-scaled), KPs (K^T, later reused for P), Vs. = 48 KB.
// grid = (SEQ/64, BATCH*NHEADS)
// ---------------------------------------------------------------------------
__global__ __launch_bounds__(256, 2)
void attn_kernel(float* __restrict__ out) {
    __shared__ float Qs[64][64];    // [d][r], pre-scaled by 1/8
    __shared__ float KPs[64][64];   // K as [d][c]; then P as [r][c]
    __shared__ float Vs[64][64];    // [c][d]

    const int qt = blockIdx.x;           // q tile, 0..15
    const int bh = blockIdx.y;           // 0..95
    const int b  = bh / NHEADS;
    const int h  = bh % NHEADS;
    const int q0 = qt * 64;

    const int tid = threadIdx.x;
    const int ty  = tid >> 4;    // row group: rows ty*4..+3
    const int tx  = tid & 15;    // col group: cols tx*4..+3

    const int lr = tid >> 2;             // 0..63 : row of the 64x64 tile
    const int lq = tid & 3;              // 0..3  : 16-col quadrant
    const size_t base = (size_t)(b * SEQ) * HID + (size_t)h * HDIM;

    // Load Q tile, transposed into [d][r], folding the 1/sqrt(64) scale.
    {
        const float* Qg = g_Q + base + (size_t)q0 * HID;
#pragma unroll
        for (int u = 0; u < 4; u++) {
            int d = lq * 16 + u * 4;
            float4 v = *(const float4*)(Qg + (size_t)lr * HID + d);
            Qs[d + 0][lr] = v.x * 0.125f;
            Qs[d + 1][lr] = v.y * 0.125f;
            Qs[d + 2][lr] = v.z * 0.125f;
            Qs[d + 3][lr] = v.w * 0.125f;
        }
    }

    float m_i[4], l_i[4], o_acc[4][4];
#pragma unroll
    for (int i = 0; i < 4; i++) {
        m_i[i] = -1e30f;
        l_i[i] = 0.0f;
#pragma unroll
        for (int j = 0; j < 4; j++) o_acc[i][j] = 0.0f;
    }

    for (int kt = 0; kt < SEQ / 64; kt++) {
        __syncthreads();   // previous iter's reads of KPs/Vs must be done

        const float* Kg = g_K + base + (size_t)(kt * 64) * HID;
        const float* Vg = g_V + base + (size_t)(kt * 64) * HID;
#pragma unroll
        for (int u = 0; u < 4; u++) {
            int d = lq * 16 + u * 4;
            float4 vk = *(const float4*)(Kg + (size_t)lr * HID + d);
            KPs[d + 0][lr] = vk.x;
            KPs[d + 1][lr] = vk.y;
            KPs[d + 2][lr] = vk.z;
            KPs[d + 3][lr] = vk.w;
            float4 vv = *(const float4*)(Vg + (size_t)lr * HID + d);
            *(float4*)&Vs[lr][d] = vv;
        }
        __syncthreads();

        // S tile: s[i][j] = sum_d Qs[d][ty*4+i] * KPs[d][tx*4+j]
        float s[4][4];
#pragma unroll
        for (int i = 0; i < 4; i++)
#pragma unroll
            for (int j = 0; j < 4; j++) s[i][j] = 0.0f;

#pragma unroll
        for (int d = 0; d < 64; d++) {
            float a[4], bf[4];
            *(float4*)a  = *(const float4*)&Qs[d][ty * 4];
            *(float4*)bf = *(const float4*)&KPs[d][tx * 4];
#pragma unroll
            for (int i = 0; i < 4; i++)
#pragma unroll
                for (int j = 0; j < 4; j++)
                    s[i][j] += a[i] * bf[j];
        }

        // Online softmax per row (row stats replicated across the 16 tx lanes).
#pragma unroll
        for (int i = 0; i < 4; i++) {
            float rm = fmaxf(fmaxf(s[i][0], s[i][1]), fmaxf(s[i][2], s[i][3]));
#pragma unroll
            for (int off = 8; off >= 1; off >>= 1)
                rm = fmaxf(rm, __shfl_xor_sync(0xffffffffu, rm, off, 16));
            float mn = fmaxf(m_i[i], rm);
            float alpha = __expf(m_i[i] - mn);
            m_i[i] = mn;
            float rs = 0.0f;
#pragma unroll
            for (int j = 0; j < 4; j++) {
                s[i][j] = __expf(s[i][j] - mn);
                rs += s[i][j];
            }
#pragma unroll
            for (int off = 8; off >= 1; off >>= 1)
                rs += __shfl_xor_sync(0xffffffffu, rs, off, 16);
            l_i[i] = l_i[i] * alpha + rs;
#pragma unroll
            for (int j = 0; j < 4; j++) o_acc[i][j] *= alpha;
        }

        __syncthreads();   // everyone finished reading K from KPs
        // Stage P into KPs as [r][c] (float4 writes, conflict-free).
#pragma unroll
        for (int i = 0; i < 4; i++)
            *(float4*)&KPs[ty * 4 + i][tx * 4] =
                make_float4(s[i][0], s[i][1], s[i][2], s[i][3]);
        __syncthreads();

        // O += P @ V : o[i][j] += sum_c P[ty*4+i][c] * Vs[c][tx*4+j]
#pragma unroll
        for (int c = 0; c < 64; c++) {
            float bf[4];
            *(float4*)bf = *(const float4*)&Vs[c][tx * 4];
#pragma unroll
            for (int i = 0; i < 4; i++) {
                float a = KPs[ty * 4 + i][c];   // broadcast within half-warp
#pragma unroll
                for (int j = 0; j < 4; j++)
                    o_acc[i][j] += a * bf[j];
            }
        }
    }

    // Normalize and write out: out[b, q0+r, h*64 + d]
#pragma unroll
    for (int i = 0; i < 4; i++) {
        float inv = 1.0f / l_i[i];
        float4 v = make_float4(o_acc[i][0] * inv, o_acc[i][1] * inv,
                               o_acc[i][2] * inv, o_acc[i][3] * inv);
        *(float4*)(out + base + (size_t)(q0 + ty * 4 + i) * HID + tx * 4) = v;
    }
}

// ---------------------------------------------------------------------------
extern "C" void kernel_launch(void* const* d_in, const int* in_sizes, int n_in,
                              void* d_out, int out_size) {
    const float* x  = (const float*)d_in[0];   // hidden_states [8,1024,768]
    const float* wq = (const float*)d_in[1];   // [768,768]
    const float* wk = (const float*)d_in[2];
    const float* wv = (const float*)d_in[3];
    float* out = (float*)d_out;                // [8,1024,768]

    dim3 g1(HID / 128, MTOT / 128, 3);
    qkv_gemm<<<g1, 256>>>(x, wq, wk, wv);

    dim3 g2(SEQ / 64, BATCH * NHEADS);
    attn_kernel<<<g2, 256>>>(out);
}

// round 3
// speedup vs baseline: 2.3058x; 2.3058x over previous
#include <cuda_runtime.h>
#include <cuda_bf16.h>
#include <cstdint>

#define HID 768
#define SEQ 1024
#define BATCH 8
#define NHEADS 12
#define MTOT (BATCH * SEQ)   // 8192

// split-bf16 operands for projection GEMM
__device__ __nv_bfloat16 g_Xh[(size_t)MTOT * HID];
__device__ __nv_bfloat16 g_Xl[(size_t)MTOT * HID];
__device__ __nv_bfloat16 g_Wh[3][(size_t)HID * HID];
__device__ __nv_bfloat16 g_Wl[3][(size_t)HID * HID];
// split-bf16 Q/K/V (Q pre-scaled by 0.125)
__device__ __nv_bfloat16 g_Qh[(size_t)MTOT * HID];
__device__ __nv_bfloat16 g_Ql[(size_t)MTOT * HID];
__device__ __nv_bfloat16 g_Kh[(size_t)MTOT * HID];
__device__ __nv_bfloat16 g_Kl[(size_t)MTOT * HID];
__device__ __nv_bfloat16 g_Vh[(size_t)MTOT * HID];
__device__ __nv_bfloat16 g_Vl[(size_t)MTOT * HID];

// ---------------------------------------------------------------------------
// helpers
// ---------------------------------------------------------------------------
__device__ __forceinline__ uint32_t smem_u32(const void* p) {
    uint32_t a;
    asm("{ .reg .u64 t; cvta.to.shared.u64 t, %1; cvt.u32.u64 %0, t; }"
        : "=r"(a) : "l"(p));
    return a;
}

#define LDMX4(R, addr)                                                        \
    asm volatile("ldmatrix.sync.aligned.m8n8.x4.shared.b16 {%0,%1,%2,%3}, [%4];" \
                 : "=r"((R)[0]), "=r"((R)[1]), "=r"((R)[2]), "=r"((R)[3])     \
                 : "r"(addr))

#define LDMX4T(R, addr)                                                       \
    asm volatile("ldmatrix.sync.aligned.m8n8.x4.trans.shared.b16 {%0,%1,%2,%3}, [%4];" \
                 : "=r"((R)[0]), "=r"((R)[1]), "=r"((R)[2]), "=r"((R)[3])     \
                 : "r"(addr))

#define MMA(C, A, b0, b1)                                                     \
    asm volatile("mma.sync.aligned.m16n8k16.row.col.f32.bf16.bf16.f32 "       \
                 "{%0,%1,%2,%3},{%4,%5,%6,%7},{%8,%9},{%0,%1,%2,%3};"         \
                 : "+f"((C)[0]), "+f"((C)[1]), "+f"((C)[2]), "+f"((C)[3])     \
                 : "r"((A)[0]), "r"((A)[1]), "r"((A)[2]), "r"((A)[3]),        \
                   "r"(b0), "r"(b1))

#define CP_ASYNC16(dst, src)                                                  \
    asm volatile("cp.async.cg.shared.global [%0], [%1], 16;"                  \
                 :: "r"(dst), "l"(src))
#define CP_COMMIT() asm volatile("cp.async.commit_group;" ::: "memory")
#define CP_WAIT1()  asm volatile("cp.async.wait_group 1;" ::: "memory")
#define CP_WAIT0()  asm volatile("cp.async.wait_group 0;" ::: "memory")

__device__ __forceinline__ void split2(float x, float y,
                                       uint32_t& hi, uint32_t& lo) {
    __nv_bfloat16 hx = __float2bfloat16(x);
    __nv_bfloat16 hy = __float2bfloat16(y);
    __nv_bfloat16 lx = __float2bfloat16(x - __bfloat162float(hx));
    __nv_bfloat16 ly = __float2bfloat16(y - __bfloat162float(hy));
    hi = ((uint32_t)__bfloat16_as_ushort(hy) << 16) | __bfloat16_as_ushort(hx);
    lo = ((uint32_t)__bfloat16_as_ushort(ly) << 16) | __bfloat16_as_ushort(lx);
}

// ---------------------------------------------------------------------------
// Kernel 0: split fp32 -> bf16 hi + lo
// ---------------------------------------------------------------------------
__global__ void split_bf16_kernel(const float* __restrict__ src,
                                  __nv_bfloat16* __restrict__ hi,
                                  __nv_bfloat16* __restrict__ lo, int n4) {
    int i = blockIdx.x * blockDim.x + threadIdx.x;
    if (i >= n4) return;
    float4 v = ((const float4*)src)[i];
    uint32_t h01, l01, h23, l23;
    split2(v.x, v.y, h01, l01);
    split2(v.z, v.w, h23, l23);
    ((uint2*)hi)[i] = make_uint2(h01, h23);
    ((uint2*)lo)[i] = make_uint2(l01, l23);
}

// ---------------------------------------------------------------------------
// Kernel 1: projection GEMM on mma.sync bf16, split-3 compensated.
// C = X @ W^T. BM=BN=128, BK=32, 2-stage cp.async. 256 thr, warp tile 32x64.
// Epilogue writes bf16 hi/lo directly (Q scaled by 0.125).
// grid = (6, 64, 3)
// ---------------------------------------------------------------------------
#define GSTG 10240   // 128 rows * 80 B (32 bf16 + 8 pad)
#define GEMM_SMEM (8 * GSTG)

__device__ __forceinline__ void gemm_load_stage(
    uint32_t sb, int st, int k0,
    const __nv_bfloat16* __restrict__ Ah, const __nv_bfloat16* __restrict__ Al,
    const __nv_bfloat16* __restrict__ Bh, const __nv_bfloat16* __restrict__ Bl,
    int m0, int n0, int tid) {
#pragma unroll
    for (int mat = 0; mat < 4; mat++) {
        const __nv_bfloat16* g =
            (mat == 0) ? Ah : (mat == 1) ? Al : (mat == 2) ? Bh : Bl;
        const int r0 = (mat < 2) ? m0 : n0;
#pragma unroll
        for (int c = 0; c < 2; c++) {
            int id = tid * 2 + c;          // 0..511
            int row = id >> 2, cc = id & 3;
            const __nv_bfloat16* gp = g + (size_t)(r0 + row) * HID + k0 + cc * 8;
            uint32_t d = sb + (uint32_t)(mat * 2 + st) * GSTG + row * 80 + cc * 16;
            CP_ASYNC16(d, gp);
        }
    }
}

__global__ __launch_bounds__(256, 1)
void qkv_gemm_mma() {
    extern __shared__ char sm[];
    const uint32_t sb = smem_u32(sm);
    const int tid = threadIdx.x;
    const int wid = tid >> 5, lane = tid & 31;
    const int wm = wid & 3, wn = wid >> 2;     // warp tile: rows wm*32, cols wn*64

    const int z = blockIdx.z;
    const int m0 = blockIdx.y * 128;
    const int n0 = blockIdx.x * 128;
    const __nv_bfloat16* Bh = g_Wh[z];
    const __nv_bfloat16* Bl = g_Wl[z];

    float c[2][8][4];
#pragma unroll
    for (int i = 0; i < 2; i++)
#pragma unroll
        for (int j = 0; j < 8; j++)
#pragma unroll
            for (int q = 0; q < 4; q++) c[i][j][q] = 0.0f;

    // ldmatrix lane addressing pieces
    const int t4 = lane >> 3, r8 = lane & 7;
    const int a_row = (r8 + (t4 & 1) * 8);          // + tile row base
    const int a_cb  = (t4 >> 1) * 16;
    const int b_row = ((t4 >> 1) * 8 + r8);
    const int b_cb  = (t4 & 1) * 16;

    gemm_load_stage(sb, 0, 0, g_Xh, g_Xl, Bh, Bl, m0, n0, tid);
    CP_COMMIT();

    const int NK = HID / 32;   // 24
    for (int s = 0; s < NK; s++) {
        if (s + 1 < NK) {
            gemm_load_stage(sb, (s + 1) & 1, (s + 1) * 32, g_Xh, g_Xl, Bh, Bl,
                            m0, n0, tid);
            CP_COMMIT();
            CP_WAIT1();
        } else {
            CP_WAIT0();
        }
        __syncthreads();

        const int st = s & 1;
        const uint32_t aH = sb + (0 * 2 + st) * GSTG;
        const uint32_t aL = sb + (1 * 2 + st) * GSTG;
        const uint32_t bH = sb + (2 * 2 + st) * GSTG;
        const uint32_t bL = sb + (3 * 2 + st) * GSTG;

#pragma unroll
        for (int kk = 0; kk < 2; kk++) {
            uint32_t ah[2][4], al[2][4];
#pragma unroll
            for (int mf = 0; mf < 2; mf++) {
                uint32_t off = (uint32_t)(wm * 32 + mf * 16 + a_row) * 80 +
                               a_cb + kk * 32;
                LDMX4(ah[mf], aH + off);
                LDMX4(al[mf], aL + off);
            }
#pragma unroll
            for (int nj = 0; nj < 4; nj++) {
                uint32_t bh[4], bl[4];
                uint32_t off = (uint32_t)(wn * 64 + nj * 16 + b_row) * 80 +
                               b_cb + kk * 32;
                LDMX4(bh, bH + off);
                LDMX4(bl, bL + off);
#pragma unroll
                for (int mf = 0; mf < 2; mf++) {
                    MMA(c[mf][2 * nj], ah[mf], bh[0], bh[1]);
                    MMA(c[mf][2 * nj], ah[mf], bl[0], bl[1]);
                    MMA(c[mf][2 * nj], al[mf], bh[0], bh[1]);
                    MMA(c[mf][2 * nj + 1], ah[mf], bh[2], bh[3]);
                    MMA(c[mf][2 * nj + 1], ah[mf], bl[2], bl[3]);
                    MMA(c[mf][2 * nj + 1], al[mf], bh[2], bh[3]);
                }
            }
        }
        __syncthreads();
    }

    // epilogue: split-store bf16 hi/lo
    __nv_bfloat16* Oh = (z == 0) ? g_Qh : (z == 1) ? g_Kh : g_Vh;
    __nv_bfloat16* Ol = (z == 0) ? g_Ql : (z == 1) ? g_Kl : g_Vl;
    const float scale = (z == 0) ? 0.125f : 1.0f;

#pragma unroll
    for (int mf = 0; mf < 2; mf++) {
        const int row = m0 + wm * 32 + mf * 16 + (lane >> 2);
#pragma unroll
        for (int nf = 0; nf < 8; nf++) {
            const int col = n0 + wn * 64 + nf * 8 + (lane & 3) * 2;
            uint32_t h, l;
            split2(c[mf][nf][0] * scale, c[mf][nf][1] * scale, h, l);
            *(uint32_t*)(Oh + (size_t)row * HID + col) = h;
            *(uint32_t*)(Ol + (size_t)row * HID + col) = l;
            split2(c[mf][nf][2] * scale, c[mf][nf][3] * scale, h, l);
            *(uint32_t*)(Oh + (size_t)(row + 8) * HID + col) = h;
            *(uint32_t*)(Ol + (size_t)(row + 8) * HID + col) = l;
        }
    }
}

// ---------------------------------------------------------------------------
// Kernel 2: flash-attention on mma.sync bf16 split-3.
// CTA = 64 q rows of one (b,h); 4 warps (one m16 frag each); kv tiles of 64.
// smem tiles [64][72] bf16 (144 B rows, conflict-free ldmatrix).
// grid = (16, 96), 128 threads.
// ---------------------------------------------------------------------------
#define TROW 144          // bytes per smem tile row
#define TSZ  (64 * TROW)  // 9216
#define QH_O 0
#define QL_O (1 * TSZ)
#define KH_O (2 * TSZ)
#define KL_O (3 * TSZ)
#define VH_O (4 * TSZ)
#define VL_O (5 * TSZ)
#define ATTN_SMEM (6 * TSZ)

__global__ __launch_bounds__(128, 1)
void attn_mma(float* __restrict__ out) {
    extern __shared__ char sm[];
    const uint32_t sb = smem_u32(sm);
    const int tid = threadIdx.x;
    const int wid = tid >> 5, lane = tid & 31;

    const int q0 = blockIdx.x * 64;
    const int bh = blockIdx.y;
    const int b = bh / NHEADS, h = bh % NHEADS;
    const size_t gbase = (size_t)(b * SEQ) * HID + (size_t)h * 64;

    // tile loader mapping: 2 threads per row, 32 elems (4 x uint4) each
    const int lrow = tid >> 1, lseg = tid & 1;
    const uint32_t sdst_off = (uint32_t)lrow * TROW + lseg * 64;
    const size_t gsrc_off = gbase + (size_t)lrow * HID + lseg * 32;

    // load Q hi/lo
    {
        const uint4* s0 = (const uint4*)(g_Qh + gsrc_off + (size_t)q0 * HID);
        const uint4* s1 = (const uint4*)(g_Ql + gsrc_off + (size_t)q0 * HID);
        uint4* d0 = (uint4*)(sm + QH_O + sdst_off);
        uint4* d1 = (uint4*)(sm + QL_O + sdst_off);
#pragma unroll
        for (int i = 0; i < 4; i++) { d0[i] = s0[i]; d1[i] = s1[i]; }
    }
    __syncthreads();

    // ldmatrix lane pieces
    const int t4 = lane >> 3, r8 = lane & 7;
    const int a_row = r8 + (t4 & 1) * 8;
    const int a_cb  = (t4 >> 1) * 16;
    const int b_row = (t4 >> 1) * 8 + r8;
    const int b_cb  = (t4 & 1) * 16;

    // Q fragments (held in regs for the whole kv loop)
    uint32_t qh[4][4], ql[4][4];
    {
        const uint32_t ar = (uint32_t)(wid * 16 + a_row) * TROW + a_cb;
#pragma unroll
        for (int kd = 0; kd < 4; kd++) {
            LDMX4(qh[kd], sb + QH_O + ar + kd * 32);
            LDMX4(ql[kd], sb + QL_O + ar + kd * 32);
        }
    }

    float O[8][4];
#pragma unroll
    for (int f = 0; f < 8; f++)
#pragma unroll
        for (int q = 0; q < 4; q++) O[f][q] = 0.0f;
    float mrow[2] = {-1e30f, -1e30f};
    float lrow_s[2] = {0.0f, 0.0f};

    for (int kt = 0; kt < SEQ / 64; kt++) {
        __syncthreads();   // previous tile consumed
        {
            const size_t go = gsrc_off + (size_t)(kt * 64) * HID;
            const uint4* sk0 = (const uint4*)(g_Kh + go);
            const uint4* sk1 = (const uint4*)(g_Kl + go);
            const uint4* sv0 = (const uint4*)(g_Vh + go);
            const uint4* sv1 = (const uint4*)(g_Vl + go);
            uint4* dk0 = (uint4*)(sm + KH_O + sdst_off);
            uint4* dk1 = (uint4*)(sm + KL_O + sdst_off);
            uint4* dv0 = (uint4*)(sm + VH_O + sdst_off);
            uint4* dv1 = (uint4*)(sm + VL_O + sdst_off);
#pragma unroll
            for (int i = 0; i < 4; i++) {
                dk0[i] = sk0[i]; dk1[i] = sk1[i];
                dv0[i] = sv0[i]; dv1[i] = sv1[i];
            }
        }
        __syncthreads();

        // S = Q @ K^T (3 compensated products)
        float S[8][4];
#pragma unroll
        for (int f = 0; f < 8; f++)
#pragma unroll
            for (int q = 0; q < 4; q++) S[f][q] = 0.0f;

#pragma unroll
        for (int kd = 0; kd < 4; kd++) {
#pragma unroll
            for (int nj = 0; nj < 4; nj++) {
                uint32_t kbh[4], kbl[4];
                const uint32_t off =
                    (uint32_t)(nj * 16 + b_row) * TROW + b_cb + kd * 32;
                LDMX4(kbh, sb + KH_O + off);
                LDMX4(kbl, sb + KL_O + off);
                MMA(S[2 * nj], qh[kd], kbh[0], kbh[1]);
                MMA(S[2 * nj], qh[kd], kbl[0], kbl[1]);
                MMA(S[2 * nj], ql[kd], kbh[0], kbh[1]);
                MMA(S[2 * nj + 1], qh[kd], kbh[2], kbh[3]);
                MMA(S[2 * nj + 1], qh[kd], kbl[2], kbl[3]);
                MMA(S[2 * nj + 1], ql[kd], kbh[2], kbh[3]);
            }
        }

        // online softmax (rows: rr=0 -> lane>>2, rr=1 -> +8)
#pragma unroll
        for (int rr = 0; rr < 2; rr++) {
            const int i0 = rr * 2;
            float mx = mrow[rr];
#pragma unroll
            for (int f = 0; f < 8; f++)
                mx = fmaxf(mx, fmaxf(S[f][i0], S[f][i0 + 1]));
            mx = fmaxf(mx, __shfl_xor_sync(0xffffffffu, mx, 1));
            mx = fmaxf(mx, __shfl_xor_sync(0xffffffffu, mx, 2));
            const float alpha = __expf(mrow[rr] - mx);
            mrow[rr] = mx;
            float sum = 0.0f;
#pragma unroll
            for (int f = 0; f < 8; f++) {
                S[f][i0] = __expf(S[f][i0] - mx);
                S[f][i0 + 1] = __expf(S[f][i0 + 1] - mx);
                sum += S[f][i0] + S[f][i0 + 1];
            }
            sum += __shfl_xor_sync(0xffffffffu, sum, 1);
            sum += __shfl_xor_sync(0xffffffffu, sum, 2);
            lrow_s[rr] = lrow_s[rr] * alpha + sum;
#pragma unroll
            for (int f = 0; f < 8; f++) {
                O[f][i0] *= alpha;
                O[f][i0 + 1] *= alpha;
            }
        }

        // O += P @ V (P split to bf16 hi/lo in regs; V via ldmatrix.trans)
#pragma unroll
        for (int t = 0; t < 4; t++) {
            uint32_t pah[4], pal[4];
            split2(S[2 * t][0], S[2 * t][1], pah[0], pal[0]);
            split2(S[2 * t][2], S[2 * t][3], pah[1], pal[1]);
            split2(S[2 * t + 1][0], S[2 * t + 1][1], pah[2], pal[2]);
            split2(S[2 * t + 1][2], S[2 * t + 1][3], pah[3], pal[3]);
#pragma unroll
            for (int jp = 0; jp < 4; jp++) {
                uint32_t vh[4], vl[4];
                const uint32_t off = (uint32_t)(t * 16 + a_row) * TROW +
                                     jp * 32 + a_cb;
                LDMX4T(vh, sb + VH_O + off);
                LDMX4T(vl, sb + VL_O + off);
                MMA(O[2 * jp], pah, vh[0], vh[1]);
                MMA(O[2 * jp], pah, vl[0], vl[1]);
                MMA(O[2 * jp], pal, vh[0], vh[1]);
                MMA(O[2 * jp + 1], pah, vh[2], vh[3]);
                MMA(O[2 * jp + 1], pah, vl[2], vl[3]);
                MMA(O[2 * jp + 1], pal, vh[2], vh[3]);
            }
        }
    }

    // normalize + write
    const float inv0 = 1.0f / lrow_s[0];
    const float inv1 = 1.0f / lrow_s[1];
    const int rowg = q0 + wid * 16 + (lane >> 2);
#pragma unroll
    for (int f = 0; f < 8; f++) {
        const int col = f * 8 + (lane & 3) * 2;
        *(float2*)(out + gbase + (size_t)rowg * HID + col) =
            make_float2(O[f][0] * inv0, O[f][1] * inv0);
        *(float2*)(out + gbase + (size_t)(rowg + 8) * HID + col) =
            make_float2(O[f][2] * inv1, O[f][3] * inv1);
    }
}

// ---------------------------------------------------------------------------
extern "C" void kernel_launch(void* const* d_in, const int* in_sizes, int n_in,
                              void* d_out, int out_size) {
    const float* x = (const float*)d_in[0];
    const float* wq = (const float*)d_in[1];
    const float* wk = (const float*)d_in[2];
    const float* wv = (const float*)d_in[3];
    float* out = (float*)d_out;

    __nv_bfloat16 *xh, *xl, *wh0, *wl0;
    cudaGetSymbolAddress((void**)&xh, g_Xh);
    cudaGetSymbolAddress((void**)&xl, g_Xl);
    cudaGetSymbolAddress((void**)&wh0, g_Wh);
    cudaGetSymbolAddress((void**)&wl0, g_Wl);

    const int nx4 = MTOT * HID / 4;
    const int nw4 = HID * HID / 4;
    split_bf16_kernel<<<(nx4 + 255) / 256, 256>>>(x, xh, xl, nx4);
    split_bf16_kernel<<<(nw4 + 255) / 256, 256>>>(
        wq, wh0, wl0, nw4);
    split_bf16_kernel<<<(nw4 + 255) / 256, 256>>>(
        wk, wh0 + (size_t)HID * HID, wl0 + (size_t)HID * HID, nw4);
    split_bf16_kernel<<<(nw4 + 255) / 256, 256>>>(
        wv, wh0 + 2 * (size_t)HID * HID, wl0 + 2 * (size_t)HID * HID, nw4);

    cudaFuncSetAttribute(qkv_gemm_mma,
                         cudaFuncAttributeMaxDynamicSharedMemorySize, GEMM_SMEM);
    dim3 g1(HID / 128, MTOT / 128, 3);
    qkv_gemm_mma<<<g1, 256, GEMM_SMEM>>>();

    cudaFuncSetAttribute(attn_mma,
                         cudaFuncAttributeMaxDynamicSharedMemorySize, ATTN_SMEM);
    dim3 g2(SEQ / 64, BATCH * NHEADS);
    attn_mma<<<g2, 128, ATTN_SMEM>>>(out);
}